// round 4
// baseline (speedup 1.0000x reference)
#include <cuda_runtime.h>

// Problem constants (fixed by the dataset shapes)
#define HWC   65536      // 256*256
#define BATCH 64
#define NATT  4096
#define MREP  2048

// Deep-batch single-wave grid: every thread issues 48 gathers.
// blocks [0, REP_BLOCKS): 2 repel items/thread  (2x24 loads)
// blocks [REP_BLOCKS, TOT_BLOCKS): 4 attract items/thread (4x12 loads)
#define REP_BLOCKS ((BATCH * MREP) / (2 * 256))  // 256
#define ATT_BLOCKS ((BATCH * NATT) / (4 * 256))  // 256
#define TOT_BLOCKS (REP_BLOCKS + ATT_BLOCKS)     // 512

// Global accumulators: [0]=S_attract, [1]=N_attract, [2]=S_repel, [3]=N_repel
// Zero-initialized at module load; the finalizing block re-zeros them each call
// so graph replays are deterministic.
__device__ double g_acc[4];
__device__ unsigned int g_done;

__device__ __forceinline__ float iou_f(float hA, float yA, float xA,
                                       float hB, float yB, float xB) {
    float areaA = hA * hA * 0.41f;
    float areaB = hB * hB * 0.41f;
    float y_min_max = fmaxf(yA - hA * 0.5f,         yB - hB * 0.5f);
    float x_min_max = fmaxf(xA - 0.41f * hA * 0.5f, xB - 0.41f * hB * 0.5f);
    float y_max_min = fminf(yA + hA * 0.5f,         yB + hB * 0.5f);
    float x_max_min = fminf(xA + 0.41f * hA * 0.5f, xB + 0.41f * hB * 0.5f);
    float I = fmaxf(y_max_min - y_min_max, 0.0f) * fmaxf(x_max_min - x_min_max, 0.0f);
    float U = areaA + areaB - I;
    return I / (U + 1e-6f);
}

// Block-wide reduction of (v0, v1) -> double atomics. blockDim.x == 256.
__device__ __forceinline__ void block_reduce2(float v0, float v1,
                                              double* acc0, double* acc1) {
    #pragma unroll
    for (int o = 16; o > 0; o >>= 1) {
        v0 += __shfl_down_sync(0xFFFFFFFFu, v0, o);
        v1 += __shfl_down_sync(0xFFFFFFFFu, v1, o);
    }
    __shared__ float s0[8], s1[8];
    int lane = threadIdx.x & 31;
    int warp = threadIdx.x >> 5;
    if (lane == 0) { s0[warp] = v0; s1[warp] = v1; }
    __syncthreads();
    if (warp == 0) {
        v0 = (lane < 8) ? s0[lane] : 0.0f;
        v1 = (lane < 8) ? s1[lane] : 0.0f;
        #pragma unroll
        for (int o = 4; o > 0; o >>= 1) {
            v0 += __shfl_down_sync(0x000000FFu, v0, o);
            v1 += __shfl_down_sync(0x000000FFu, v1, o);
        }
        if (lane == 0) {
            atomicAdd(acc0, (double)v0);
            atomicAdd(acc1, (double)v1);
        }
    }
}

__global__ __launch_bounds__(256, 4)
void fused_iou_loss_kernel(const float* __restrict__ oh,
                           const float* __restrict__ ooff,
                           const float* __restrict__ pre_off,
                           const int*   __restrict__ attract,
                           const int*   __restrict__ repel,
                           const unsigned char* __restrict__ mask_att,
                           const unsigned char* __restrict__ mask_rep,
                           float* __restrict__ out) {
    if (blockIdx.x < REP_BLOCKS) {
        // ---------- repel branch: two items per thread, 2x24 = 48 gathers ----------
        int w    = blockIdx.x * 256 + threadIdx.x;   // [0, B*MREP/2)
        int gid0 = 2 * w;                            // even item; pair shares batch
        int b    = gid0 >> 11;                       // / 2048 (MREP even -> same b)

        const int4* rp = reinterpret_cast<const int4*>(repel) + (size_t)gid0 * 2;
        int4 q[4];
        #pragma unroll
        for (int j = 0; j < 4; j++) q[j] = rp[j];
        unsigned short mr = reinterpret_cast<const unsigned short*>(mask_rep)[w];
        float4 po2 = reinterpret_cast<const float4*>(pre_off)[w];  // 2x float2

        const float* ohb = oh   + (size_t)b * HWC;
        const float* o0b = ooff + (size_t)b * 2 * HWC;
        const float* o1b = o0b + HWC;

        int ind[16] = {q[0].x, q[0].y, q[0].z, q[0].w,
                       q[1].x, q[1].y, q[1].z, q[1].w,
                       q[2].x, q[2].y, q[2].z, q[2].w,
                       q[3].x, q[3].y, q[3].z, q[3].w};
        float hs[16], a0[16], a1[16];
        #pragma unroll
        for (int k = 0; k < 16; k++) {
            hs[k] = __ldg(ohb + ind[k]);
            a0[k] = __ldg(o0b + ind[k]);
            a1[k] = __ldg(o1b + ind[k]);
        }

        float lsum = 0.f, cnt = 0.f;
        #pragma unroll
        for (int it = 0; it < 2; it++) {
            float hmean[2], y[2], x[2];
            #pragma unroll
            for (int j = 0; j < 2; j++) {
                int base = it * 8 + j * 4;
                float hsum = 0.f, s0 = 0.f, s1 = 0.f;
                #pragma unroll
                for (int k = 0; k < 4; k++) {
                    hsum += hs[base + k];
                    s0   += a0[base + k];
                    s1   += a1[base + k];
                }
                hmean[j] = hsum * 0.25f;
                // mean of (off + OFFSETS): OFFSETS contributes +0.5 per channel
                y[j] = s0 * 0.25f + 0.5f;
                x[j] = s1 * 0.25f + 0.5f;
            }
            float pox = (it == 0) ? po2.x : po2.z;
            float poy = (it == 0) ? po2.y : po2.w;
            y[1] += pox;
            x[1] += poy;

            float v = iou_f(expf(hmean[0]), y[0], x[0],
                            expf(hmean[1]), y[1], x[1]);
            if ((mr >> (8 * it)) & 0xFFu) { lsum += v; cnt += 1.0f; }
        }
        block_reduce2(lsum, cnt, &g_acc[2], &g_acc[3]);
    } else {
        // ---------- attract branch: four items per thread, 4x12 = 48 gathers ----------
        int w    = (blockIdx.x - REP_BLOCKS) * 256 + threadIdx.x;  // [0, B*NATT/4)
        int gid0 = 4 * w;                                          // NATT%4==0 -> same b
        int b    = gid0 >> 12;                                     // / 4096

        const int4* ap = reinterpret_cast<const int4*>(attract) + gid0;
        int4 q[4];
        #pragma unroll
        for (int j = 0; j < 4; j++) q[j] = ap[j];
        uint4 m4v = reinterpret_cast<const uint4*>(mask_att)[w];
        unsigned int mm[4] = {m4v.x, m4v.y, m4v.z, m4v.w};

        const float* ohb = oh   + (size_t)b * HWC;
        const float* o0b = ooff + (size_t)b * 2 * HWC;
        const float* o1b = o0b + HWC;

        int ind[16] = {q[0].x, q[0].y, q[0].z, q[0].w,
                       q[1].x, q[1].y, q[1].z, q[1].w,
                       q[2].x, q[2].y, q[2].z, q[2].w,
                       q[3].x, q[3].y, q[3].z, q[3].w};
        float h[16], o0[16], o1[16];
        #pragma unroll
        for (int k = 0; k < 16; k++) {
            h[k]  = __ldg(ohb + ind[k]);
            o0[k] = __ldg(o0b + ind[k]);
            o1[k] = __ldg(o1b + ind[k]);
        }

        // OFFSETS = [[0,0],[1,0],[0,1],[1,1]] added to (o0, o1)
        const float kx[4] = {0.f, 1.f, 0.f, 1.f};
        const float ky[4] = {0.f, 0.f, 1.f, 1.f};

        float lsum = 0.f, cnt = 0.f;
        #pragma unroll
        for (int it = 0; it < 4; it++) {
            int base = it * 4;
            float hm = 0.f, o0m = 0.f, o1m = 0.f;
            float co0[4], co1[4];
            #pragma unroll
            for (int k = 0; k < 4; k++) {
                co0[k] = o0[base + k] + kx[k];
                co1[k] = o1[base + k] + ky[k];
                hm  += h[base + k];
                o0m += co0[k];
                o1m += co1[k];
            }
            hm *= 0.25f; o0m *= 0.25f; o1m *= 0.25f;
            float hB = expf(hm);

            unsigned int m = mm[it];
            #pragma unroll
            for (int k = 0; k < 4; k++) {
                if ((m >> (8 * k)) & 0xFFu) {
                    lsum += 1.0f - iou_f(expf(h[base + k]), co0[k], co1[k],
                                         hB, o0m, o1m);
                    cnt  += 1.0f;
                }
            }
        }
        block_reduce2(lsum, cnt, &g_acc[0], &g_acc[1]);
    }

    // ---------------- last-block finalize + reset ----------------
    __threadfence();
    __shared__ bool s_last;
    if (threadIdx.x == 0) {
        unsigned int ticket = atomicAdd(&g_done, 1u);
        s_last = (ticket == (unsigned int)(TOT_BLOCKS - 1));
    }
    __syncthreads();
    if (s_last && threadIdx.x == 0) {
        double sa = g_acc[0], na = g_acc[1];
        double sr = g_acc[2], nr = g_acc[3];
        out[0] = (float)(sa / (na + 1e-4) + sr / (nr + 1e-4));
        g_acc[0] = 0.0; g_acc[1] = 0.0; g_acc[2] = 0.0; g_acc[3] = 0.0;
        __threadfence();
        g_done = 0u;
    }
}

extern "C" void kernel_launch(void* const* d_in, const int* in_sizes, int n_in,
                              void* d_out, int out_size) {
    const float* output_h    = (const float*)d_in[0];  // [64,1,256,256]
    const float* output_off  = (const float*)d_in[1];  // [64,2,256,256]
    // d_in[2], d_in[3]: target_h / target_off — unused by the reference
    const float* pre_off     = (const float*)d_in[4];  // [64,2048,2]
    const int*   attract     = (const int*)  d_in[5];  // [64,4096,4]
    const int*   repel       = (const int*)  d_in[6];  // [64,2048,2,4]
    const unsigned char* mask_attract = (const unsigned char*)d_in[7];  // [64,4096,4] bool
    const unsigned char* mask_repel   = (const unsigned char*)d_in[8];  // [64,2048,1] bool
    float* out = (float*)d_out;

    fused_iou_loss_kernel<<<TOT_BLOCKS, 256>>>(
        output_h, output_off, pre_off, attract, repel,
        mask_attract, mask_repel, out);
}